// round 8
// baseline (speedup 1.0000x reference)
#include <cuda_runtime.h>
#include <cuda_fp16.h>
#include <math.h>
#include <mma.h>

using namespace nvcuda;

// ---------------- model constants ----------------
constexpr int Dm  = 768;
constexpr int DIm = 1536;
constexpr int Nst = 16;
constexpr int NLs = 8;
constexpr int Bb  = 2;
constexpr int Ll  = 1024;
constexpr int Mrows = Bb * Ll;          // 2048
constexpr float EPSf = 1e-5f;
constexpr int CH = 16;                  // scan chunks
constexpr int CL = Ll / CH;             // 64 steps per chunk
constexpr int DBL_LD = 128;             // padded dbl row stride

// ---------------- fp32 scratch ----------------
constexpr size_t OFF_RES = 0;
constexpr size_t OFF_H   = OFF_RES + (size_t)Mrows * Dm;
constexpr size_t OFF_X   = OFF_H   + (size_t)Mrows * Dm;
constexpr size_t OFF_XZ  = OFF_X   + (size_t)Mrows * Dm;
constexpr size_t OFF_XC  = OFF_XZ  + (size_t)Mrows * 2 * DIm;
constexpr size_t OFF_DT  = OFF_XC  + (size_t)Mrows * DIm;       // dt_lin
constexpr size_t OFF_Y   = OFF_DT  + (size_t)Mrows * DIm;
constexpr size_t OFF_DBL = OFF_Y   + (size_t)Mrows * DIm;       // Mrows x 128
constexpr size_t CHSZ    = (size_t)Bb * CH * DIm * Nst;
constexpr size_t OFF_CHE = OFF_DBL + (size_t)Mrows * DBL_LD;
constexpr size_t OFF_APR = OFF_CHE + CHSZ;
constexpr size_t OFF_PRE = OFF_APR + CHSZ;
constexpr size_t SCRATCH_TOTAL = OFF_PRE + CHSZ;

__device__ float g_scratch[SCRATCH_TOTAL];

// ---------------- fp16 weight scratch ----------------
constexpr size_t HSZ_IN  = (size_t)NLs * 2 * DIm * Dm;    // in_proj
constexpr size_t HSZ_OUT = (size_t)NLs * Dm * DIm;        // out_proj
constexpr size_t HSZ_XW  = (size_t)NLs * 128 * DIm;       // x_proj padded N=128
constexpr size_t HSZ_DW  = (size_t)NLs * DIm * 64;        // dt_proj padded K=64
constexpr size_t HOFF_IN  = 0;
constexpr size_t HOFF_OUT = HOFF_IN  + HSZ_IN;
constexpr size_t HOFF_XW  = HOFF_OUT + HSZ_OUT;
constexpr size_t HOFF_DW  = HOFF_XW  + HSZ_XW;
constexpr size_t HTOTAL   = HOFF_DW  + HSZ_DW;

__device__ __half g_wh[HTOTAL];

// ---------------- cp.async helpers ----------------
__device__ __forceinline__ void cp16(void* smem_ptr, const void* gmem_ptr)
{
    unsigned s = (unsigned)__cvta_generic_to_shared(smem_ptr);
    asm volatile("cp.async.cg.shared.global [%0], [%1], 16;\n" :: "r"(s), "l"(gmem_ptr));
}
__device__ __forceinline__ void cp_commit()
{
    asm volatile("cp.async.commit_group;\n" ::: "memory");
}
template <int N>
__device__ __forceinline__ void cp_wait()
{
    asm volatile("cp.async.wait_group %0;\n" :: "n"(N) : "memory");
}

// ---------------- vectorized fp32 -> fp16 helpers ----------------
__device__ __forceinline__ uint4 pack8(const float4& a, const float4& b)
{
    __half2 h0 = __floats2half2_rn(a.x, a.y);
    __half2 h1 = __floats2half2_rn(a.z, a.w);
    __half2 h2 = __floats2half2_rn(b.x, b.y);
    __half2 h3 = __floats2half2_rn(b.z, b.w);
    uint4 o;
    o.x = *(const unsigned*)&h0;
    o.y = *(const unsigned*)&h1;
    o.z = *(const unsigned*)&h2;
    o.w = *(const unsigned*)&h3;
    return o;
}

// plain convert: 8 elements per thread (n must be multiple of 8)
__global__ void conv_w8_kernel(const float4* __restrict__ src,
                               uint4* __restrict__ dst, int n8)
{
    int i = blockIdx.x * blockDim.x + threadIdx.x;
    if (i >= n8) return;
    float4 a = src[2 * i];
    float4 b = src[2 * i + 1];
    dst[i] = pack8(a, b);
}

// x_proj pad: dst [NL][128][DIm] halves; rows r>=80 are zero. 8 k per thread.
__global__ void pad_xw8_kernel(const float* __restrict__ xw, uint4* __restrict__ dst)
{
    constexpr int KV = DIm / 8;   // 192 vec-units per row
    int idx = blockIdx.x * blockDim.x + threadIdx.x;
    if (idx >= NLs * 128 * KV) return;
    int l = idx / (128 * KV);
    int rem = idx - l * (128 * KV);
    int r = rem / KV;
    int kv = rem - r * KV;
    if (r < 80) {
        const float4* srow = (const float4*)(xw + ((size_t)l * 80 + r) * DIm) + 2 * kv;
        dst[idx] = pack8(srow[0], srow[1]);
    } else {
        dst[idx] = make_uint4(0, 0, 0, 0);
    }
}

// dt_proj pad: dst [NL][DIm][64] halves; cols c>=48 are zero. 8 c per thread.
__global__ void pad_dw8_kernel(const float* __restrict__ dw, uint4* __restrict__ dst)
{
    constexpr int CV = 64 / 8;    // 8 vec-units per row
    int idx = blockIdx.x * blockDim.x + threadIdx.x;
    if (idx >= NLs * DIm * CV) return;
    int ld = idx / CV;            // l*DIm + d
    int cv = idx - ld * CV;
    if (cv < 6) {                 // cols 0..47
        const float4* srow = (const float4*)(dw + (size_t)ld * 48) + 2 * cv;
        dst[idx] = pack8(srow[0], srow[1]);
    } else {
        dst[idx] = make_uint4(0, 0, 0, 0);
    }
}

// ---------------- embedding gather ----------------
__global__ void embed_kernel(const int* __restrict__ ids,
                             const float* __restrict__ emb,
                             float* __restrict__ res)
{
    int idx = blockIdx.x * blockDim.x + threadIdx.x;
    if (idx >= Mrows * Dm) return;
    int row = idx / Dm;
    int c   = idx - row * Dm;
    res[idx] = emb[(size_t)ids[row] * Dm + c];
}

// ---------------- residual add + RMSNorm ----------------
__global__ void rms_resid_kernel(float* __restrict__ res,
                                 const float* __restrict__ xadd,
                                 const float* __restrict__ w,
                                 float* __restrict__ out,
                                 int addx)
{
    const int row = blockIdx.x;
    const int tid = threadIdx.x;
    float v[3];
    float local = 0.f;
#pragma unroll
    for (int j = 0; j < 3; j++) {
        int c = tid + j * 256;
        float t = res[(size_t)row * Dm + c];
        if (addx) {
            t += xadd[(size_t)row * Dm + c];
            res[(size_t)row * Dm + c] = t;
        }
        v[j] = t;
        local += t * t;
    }
#pragma unroll
    for (int o = 16; o > 0; o >>= 1) local += __shfl_xor_sync(0xffffffffu, local, o);
    __shared__ float warpsum[8];
    __shared__ float sscale;
    if ((tid & 31) == 0) warpsum[tid >> 5] = local;
    __syncthreads();
    if (tid == 0) {
        float t = 0.f;
#pragma unroll
        for (int j = 0; j < 8; j++) t += warpsum[j];
        sscale = rsqrtf(t / (float)Dm + EPSf);
    }
    __syncthreads();
    float sc = sscale;
#pragma unroll
    for (int j = 0; j < 3; j++) {
        int c = tid + j * 256;
        out[(size_t)row * Dm + c] = v[j] * sc * w[c];
    }
}

// ============================================================================
// FP16 tensor-core GEMM, fp32 accumulate.
// C[M,N] = A[M,K](fp32, lda) @ W[N,K]^T(fp16, row stride K).
// BM=128, BN in {128,64}, BK=32.  256 threads = 8 warps (2m x 4n).
// ============================================================================
template <int BN>
__global__ __launch_bounds__(256)
void hgemm_tn(const float* __restrict__ A, int lda,
              const __half* __restrict__ W,
              float* __restrict__ C, int ldc, int K)
{
    constexpr int BM = 128;
    constexpr int BK = 32;
    constexpr int LD = BK + 8;       // 40 halves = 80B rows (16B-aligned)
    constexpr int WM = 64;
    constexpr int WN = BN / 4;
    constexpr int AF = WM / 16;      // 4
    constexpr int BF = WN / 16;      // 2 or 1

    __shared__ __half As[2][BM][LD];
    __shared__ __half Ws[2][BN][LD];

    const int t    = threadIdx.x;
    const int warp = t >> 5;
    const int wm   = (warp & 1) * WM;
    const int wn   = (warp >> 1) * WN;
    const int bm   = blockIdx.y * BM;
    const int bn   = blockIdx.x * BN;

    const int arow = t >> 1;
    const int ac0  = (t & 1) * 16;
    const float* Ap = A + (size_t)(bm + arow) * lda + ac0;

    int wrow, wc0, wcn;
    if (BN == 128) { wrow = t >> 1; wc0 = (t & 1) * 16; wcn = 2; }
    else           { wrow = t >> 2; wc0 = (t & 3) * 8;  wcn = 1; }
    const __half* Wp = W + (size_t)(bn + wrow) * K + wc0;

    float4 av[4];

    auto loadA = [&](int k0) {
#pragma unroll
        for (int i = 0; i < 4; i++)
            av[i] = *(const float4*)(Ap + k0 + i * 4);
    };
    auto storeA = [&](int stage) {
#pragma unroll
        for (int i = 0; i < 4; i++) {
            __half2 h0 = __floats2half2_rn(av[i].x, av[i].y);
            __half2 h1 = __floats2half2_rn(av[i].z, av[i].w);
            *(__half2*)&As[stage][arow][ac0 + i * 4 + 0] = h0;
            *(__half2*)&As[stage][arow][ac0 + i * 4 + 2] = h1;
        }
    };
    auto issueW = [&](int stage, int k0) {
#pragma unroll
        for (int i = 0; i < 2; i++) {
            if (i < wcn)
                cp16(&Ws[stage][wrow][wc0 + i * 8], Wp + k0 + i * 8);
        }
        cp_commit();
    };

    wmma::fragment<wmma::accumulator, 16, 16, 16, float> acc[AF][BF];
#pragma unroll
    for (int i = 0; i < AF; i++)
#pragma unroll
        for (int j = 0; j < BF; j++)
            wmma::fill_fragment(acc[i][j], 0.f);

    const int nt = K / BK;

    loadA(0);
    issueW(0, 0);
    storeA(0);
    cp_wait<0>();
    __syncthreads();

    for (int tt = 0; tt < nt; ++tt) {
        const int buf = tt & 1;
        const bool more = (tt + 1 < nt);
        if (more) {
            loadA((tt + 1) * BK);
            issueW(buf ^ 1, (tt + 1) * BK);
        }

#pragma unroll
        for (int kk = 0; kk < BK; kk += 16) {
            wmma::fragment<wmma::matrix_a, 16, 16, 16, __half, wmma::row_major> af[AF];
            wmma::fragment<wmma::matrix_b, 16, 16, 16, __half, wmma::col_major> bf[BF];
#pragma unroll
            for (int i = 0; i < AF; i++)
                wmma::load_matrix_sync(af[i], &As[buf][wm + i * 16][kk], LD);
#pragma unroll
            for (int j = 0; j < BF; j++)
                wmma::load_matrix_sync(bf[j], &Ws[buf][wn + j * 16][kk], LD);
#pragma unroll
            for (int i = 0; i < AF; i++)
#pragma unroll
                for (int j = 0; j < BF; j++)
                    wmma::mma_sync(acc[i][j], af[i], bf[j], acc[i][j]);
        }

        if (more) {
            storeA(buf ^ 1);
            cp_wait<0>();
        }
        __syncthreads();
    }

#pragma unroll
    for (int i = 0; i < AF; i++)
#pragma unroll
        for (int j = 0; j < BF; j++)
            wmma::store_matrix_sync(&C[(size_t)(bm + wm + i * 16) * ldc + bn + wn + j * 16],
                                    acc[i][j], ldc, wmma::mem_row_major);
}

// ---------------- depthwise causal conv (K=4) + SiLU ----------------
__global__ void conv_silu_kernel(const float* __restrict__ xz,
                                 const float* __restrict__ w,
                                 const float* __restrict__ bias,
                                 float* __restrict__ xc)
{
    int idx = blockIdx.x * blockDim.x + threadIdx.x;
    if (idx >= Mrows * DIm) return;
    int row = idx / DIm;
    int c   = idx - row * DIm;
    int l   = row & (Ll - 1);
    float s = bias[c];
#pragma unroll
    for (int k = 0; k < 4; k++) {
        int ll = l - 3 + k;
        if (ll >= 0) s += w[c * 4 + k] * xz[(size_t)(row - 3 + k) * (2 * DIm) + c];
    }
    xc[idx] = s / (1.f + expf(-s));
}

// ============================================================================
// Chunked selective scan (3 phases), 4 lanes per channel, CH chunks of CL.
// ============================================================================
__device__ __forceinline__ float softplus_f(float x)
{
    return (x > 20.f) ? x : log1pf(__expf(x));
}

__global__ void scan_pass1(const float* __restrict__ xc,
                           const float* __restrict__ dtl,
                           const float* __restrict__ dbl,
                           const float* __restrict__ A_log,
                           const float* __restrict__ dtb_bias,
                           float* __restrict__ chk_end,
                           float* __restrict__ aprod)
{
    int gt = blockIdx.x * blockDim.x + threadIdx.x;
    int d = gt >> 2;
    int q = gt & 3;
    int c = blockIdx.y;
    int b = blockIdx.z;
    if (d >= DIm) return;

    float Ac[4], st[4] = {0.f, 0.f, 0.f, 0.f}, ap[4] = {1.f, 1.f, 1.f, 1.f};
#pragma unroll
    for (int n = 0; n < 4; n++)
        Ac[n] = -expf(A_log[(size_t)d * 16 + q * 4 + n]);
    const float db = dtb_bias[d];

    const int l0 = c * CL;
    const float* xcb = xc  + ((size_t)b * Ll + l0) * DIm + d;
    const float* dtb = dtl + ((size_t)b * Ll + l0) * DIm + d;
    const float* blb = dbl + ((size_t)b * Ll + l0) * DBL_LD + 48 + q * 4;

    for (int l = 0; l < CL; l++) {
        float u   = xcb[(size_t)l * DIm];
        float dtt = softplus_f(dtb[(size_t)l * DIm] + db);
        float du  = dtt * u;
        const float* bl = blb + (size_t)l * DBL_LD;
#pragma unroll
        for (int n = 0; n < 4; n++) {
            float e = __expf(dtt * Ac[n]);
            st[n] = fmaf(e, st[n], du * bl[n]);
            ap[n] *= e;
        }
    }
    size_t base = (((size_t)b * CH + c) * DIm + d) * 16 + q * 4;
#pragma unroll
    for (int n = 0; n < 4; n++) {
        chk_end[base + n] = st[n];
        aprod[base + n]   = ap[n];
    }
}

__global__ void scan_pass2(const float* __restrict__ chk_end,
                           const float* __restrict__ aprod,
                           float* __restrict__ chk_pref)
{
    int idx = blockIdx.x * blockDim.x + threadIdx.x;
    if (idx >= Bb * DIm * Nst) return;
    int b = idx / (DIm * Nst);
    int r = idx - b * (DIm * Nst);
    float hv = 0.f;
#pragma unroll
    for (int c = 0; c < CH; c++) {
        size_t o = ((size_t)b * CH + c) * DIm * Nst + r;
        chk_pref[o] = hv;
        hv = fmaf(aprod[o], hv, chk_end[o]);
    }
}

__global__ void scan_pass3(const float* __restrict__ xc,
                           const float* __restrict__ dtl,
                           const float* __restrict__ dbl,
                           const float* __restrict__ A_log,
                           const float* __restrict__ dtb_bias,
                           const float* __restrict__ Dp,
                           const float* __restrict__ xz,
                           const float* __restrict__ chk_pref,
                           float* __restrict__ y)
{
    int gt = blockIdx.x * blockDim.x + threadIdx.x;
    int d = gt >> 2;
    int q = gt & 3;
    int c = blockIdx.y;
    int b = blockIdx.z;
    if (d >= DIm) return;

    float Ac[4], st[4];
#pragma unroll
    for (int n = 0; n < 4; n++)
        Ac[n] = -expf(A_log[(size_t)d * 16 + q * 4 + n]);
    {
        size_t base = (((size_t)b * CH + c) * DIm + d) * 16 + q * 4;
#pragma unroll
        for (int n = 0; n < 4; n++) st[n] = chk_pref[base + n];
    }
    const float db = dtb_bias[d];
    float dp = Dp[d];

    const int l0 = c * CL;
    const float* xcb = xc  + ((size_t)b * Ll + l0) * DIm + d;
    const float* dtb = dtl + ((size_t)b * Ll + l0) * DIm + d;
    const float* zb  = xz  + ((size_t)b * Ll + l0) * (2 * DIm) + DIm + d;
    const float* blb = dbl + ((size_t)b * Ll + l0) * DBL_LD + 48 + q * 4;
    float*       yb  = y   + ((size_t)b * Ll + l0) * DIm + d;

    for (int l = 0; l < CL; l++) {
        float u   = xcb[(size_t)l * DIm];
        float dtt = softplus_f(dtb[(size_t)l * DIm] + db);
        float du  = dtt * u;
        const float* bl = blb + (size_t)l * DBL_LD;
        float yv = 0.f;
#pragma unroll
        for (int n = 0; n < 4; n++) {
            float e = __expf(dtt * Ac[n]);
            st[n] = fmaf(e, st[n], du * bl[n]);
            yv = fmaf(st[n], bl[16 + n], yv);
        }
        yv += __shfl_xor_sync(0xffffffffu, yv, 1);
        yv += __shfl_xor_sync(0xffffffffu, yv, 2);
        if (q == 0) {
            float z = zb[(size_t)l * (2 * DIm)];
            yv = fmaf(u, dp, yv);
            yb[(size_t)l * DIm] = yv * (z / (1.f + __expf(-z)));
        }
    }
}

// ---------------- host launcher ----------------
extern "C" void kernel_launch(void* const* d_in, const int* in_sizes, int n_in,
                              void* d_out, int out_size)
{
    const int*   ids       = (const int*)  d_in[0];
    const float* emb       = (const float*)d_in[1];
    const float* in_proj_w = (const float*)d_in[2];   // [NL, 2*DI, D]
    const float* conv_w    = (const float*)d_in[3];   // [NL, DI, 4]
    const float* conv_b    = (const float*)d_in[4];   // [NL, DI]
    const float* x_proj_w  = (const float*)d_in[5];   // [NL, 80, DI]
    const float* dt_proj_w = (const float*)d_in[6];   // [NL, DI, 48]
    const float* dt_proj_b = (const float*)d_in[7];   // [NL, DI]
    const float* A_log     = (const float*)d_in[8];   // [NL, DI, 16]
    const float* D_param   = (const float*)d_in[9];   // [NL, DI]
    const float* out_proj_w= (const float*)d_in[10];  // [NL, D, DI]
    const float* norm_w    = (const float*)d_in[11];  // [NL, D]
    const float* norm_f_w  = (const float*)d_in[12];  // [D]
    float* out = (float*)d_out;

    float* s = nullptr;
    cudaGetSymbolAddress((void**)&s, g_scratch);
    __half* wh = nullptr;
    cudaGetSymbolAddress((void**)&wh, g_wh);

    float* res = s + OFF_RES;
    float* h   = s + OFF_H;
    float* x   = s + OFF_X;
    float* xz  = s + OFF_XZ;
    float* xc  = s + OFF_XC;
    float* dtl = s + OFF_DT;
    float* y   = s + OFF_Y;
    float* dbl = s + OFF_DBL;
    float* che = s + OFF_CHE;
    float* apr = s + OFF_APR;
    float* pre = s + OFF_PRE;

    __half* w_in  = wh + HOFF_IN;
    __half* w_out = wh + HOFF_OUT;
    __half* w_xw  = wh + HOFF_XW;
    __half* w_dw  = wh + HOFF_DW;

    // vectorized weight conversion / padding (deterministic, every launch)
    {
        int n8 = (int)(HSZ_IN / 8);
        conv_w8_kernel<<<(n8 + 255) / 256, 256>>>((const float4*)in_proj_w,
                                                  (uint4*)w_in, n8);
        n8 = (int)(HSZ_OUT / 8);
        conv_w8_kernel<<<(n8 + 255) / 256, 256>>>((const float4*)out_proj_w,
                                                  (uint4*)w_out, n8);
        int nxw = NLs * 128 * (DIm / 8);
        pad_xw8_kernel<<<(nxw + 255) / 256, 256>>>(x_proj_w, (uint4*)w_xw);
        int ndw = NLs * DIm * (64 / 8);
        pad_dw8_kernel<<<(ndw + 255) / 256, 256>>>(dt_proj_w, (uint4*)w_dw);
    }

    embed_kernel<<<(Mrows * Dm + 255) / 256, 256>>>(ids, emb, res);

    for (int i = 0; i < NLs; i++) {
        // h = rms(res += x)
        rms_resid_kernel<<<Mrows, 256>>>(res, x, norm_w + (size_t)i * Dm, h, i > 0);

        // xz = h @ in_proj^T   [2048, 3072], K=768
        {
            dim3 g(2 * DIm / 128, Mrows / 128);
            hgemm_tn<128><<<g, 256>>>(h, Dm, w_in + (size_t)i * 2 * DIm * Dm,
                                      xz, 2 * DIm, Dm);
        }

        // xc = silu(causal depthwise conv(xi) + b)
        conv_silu_kernel<<<(Mrows * DIm + 255) / 256, 256>>>(
            xz, conv_w + (size_t)i * DIm * 4, conv_b + (size_t)i * DIm, xc);

        // dbl = xc @ xw_pad^T   [2048, 128], K=1536
        {
            dim3 g(128 / 64, Mrows / 128);
            hgemm_tn<64><<<g, 256>>>(xc, DIm, w_xw + (size_t)i * 128 * DIm,
                                     dbl, DBL_LD, DIm);
        }

        // dt_lin = dbl[:, :64] @ dw_pad^T   [2048, 1536], K=64
        {
            dim3 g(DIm / 128, Mrows / 128);
            hgemm_tn<128><<<g, 256>>>(dbl, DBL_LD, w_dw + (size_t)i * DIm * 64,
                                      dtl, DIm, 64);
        }

        // chunked selective scan
        {
            dim3 g1(DIm * 4 / 128, CH, Bb);
            scan_pass1<<<g1, 128>>>(xc, dtl, dbl, A_log + (size_t)i * DIm * Nst,
                                    dt_proj_b + (size_t)i * DIm, che, apr);
            scan_pass2<<<(Bb * DIm * Nst + 255) / 256, 256>>>(che, apr, pre);
            scan_pass3<<<g1, 128>>>(xc, dtl, dbl, A_log + (size_t)i * DIm * Nst,
                                    dt_proj_b + (size_t)i * DIm,
                                    D_param + (size_t)i * DIm, xz, pre, y);
        }

        // x = y @ out_proj^T   [2048, 768], K=1536
        {
            dim3 g(Dm / 64, Mrows / 128);
            hgemm_tn<64><<<g, 256>>>(y, DIm, w_out + (size_t)i * Dm * DIm,
                                     x, Dm, DIm);
        }
    }

    // final: out = rms(res + x) * norm_f_w
    rms_resid_kernel<<<Mrows, 256>>>(res, x, norm_f_w, out, 1);
}

// round 9
// speedup vs baseline: 1.2327x; 1.2327x over previous
#include <cuda_runtime.h>
#include <cuda_fp16.h>
#include <math.h>
#include <mma.h>

using namespace nvcuda;

// ---------------- model constants ----------------
constexpr int Dm  = 768;
constexpr int DIm = 1536;
constexpr int Nst = 16;
constexpr int NLs = 8;
constexpr int Bb  = 2;
constexpr int Ll  = 1024;
constexpr int Mrows = Bb * Ll;          // 2048
constexpr float EPSf = 1e-5f;
constexpr int CH = 16;                  // scan chunks
constexpr int CL = Ll / CH;             // 64 steps per chunk
constexpr int DBL_LD = 128;             // padded dbl row stride

// ---------------- fp32 scratch ----------------
constexpr size_t OFF_RES = 0;
constexpr size_t OFF_X   = OFF_RES + (size_t)Mrows * Dm;
constexpr size_t OFF_XZ  = OFF_X   + (size_t)Mrows * Dm;
constexpr size_t OFF_XC  = OFF_XZ  + (size_t)Mrows * 2 * DIm;
constexpr size_t OFF_DT  = OFF_XC  + (size_t)Mrows * DIm;       // dt_lin
constexpr size_t OFF_DBL = OFF_DT  + (size_t)Mrows * DIm;       // Mrows x 128
constexpr size_t CHSZ    = (size_t)Bb * CH * DIm * Nst;
constexpr size_t OFF_CHE = OFF_DBL + (size_t)Mrows * DBL_LD;
constexpr size_t OFF_APR = OFF_CHE + CHSZ;
constexpr size_t OFF_PRE = OFF_APR + CHSZ;
constexpr size_t SCRATCH_TOTAL = OFF_PRE + CHSZ;

__device__ float g_scratch[SCRATCH_TOTAL];

// ---------------- fp16 weight scratch ----------------
constexpr size_t HSZ_IN  = (size_t)NLs * 2 * DIm * Dm;    // in_proj
constexpr size_t HSZ_OUT = (size_t)NLs * Dm * DIm;        // out_proj
constexpr size_t HSZ_XW  = (size_t)NLs * 128 * DIm;       // x_proj padded N=128
constexpr size_t HSZ_DW  = (size_t)NLs * DIm * 64;        // dt_proj padded K=64
constexpr size_t HOFF_IN  = 0;
constexpr size_t HOFF_OUT = HOFF_IN  + HSZ_IN;
constexpr size_t HOFF_XW  = HOFF_OUT + HSZ_OUT;
constexpr size_t HOFF_DW  = HOFF_XW  + HSZ_XW;
constexpr size_t HTOTAL   = HOFF_DW  + HSZ_DW;

__device__ __half g_wh[HTOTAL];

// ---------------- fp16 activation scratch ----------------
constexpr size_t AOFF_H16   = 0;                                 // Mrows x Dm
constexpr size_t AOFF_XC16  = AOFF_H16  + (size_t)Mrows * Dm;    // Mrows x DIm
constexpr size_t AOFF_DBL16 = AOFF_XC16 + (size_t)Mrows * DIm;   // Mrows x 128
constexpr size_t AOFF_Y16   = AOFF_DBL16 + (size_t)Mrows * DBL_LD; // Mrows x DIm
constexpr size_t ATOTAL     = AOFF_Y16  + (size_t)Mrows * DIm;

__device__ __half g_act[ATOTAL];

// ---------------- cp.async helpers ----------------
__device__ __forceinline__ void cp16(void* smem_ptr, const void* gmem_ptr)
{
    unsigned s = (unsigned)__cvta_generic_to_shared(smem_ptr);
    asm volatile("cp.async.cg.shared.global [%0], [%1], 16;\n" :: "r"(s), "l"(gmem_ptr));
}
__device__ __forceinline__ void cp_commit()
{
    asm volatile("cp.async.commit_group;\n" ::: "memory");
}
template <int N>
__device__ __forceinline__ void cp_wait()
{
    asm volatile("cp.async.wait_group %0;\n" :: "n"(N) : "memory");
}

// ---------------- vectorized fp32 -> fp16 pack ----------------
__device__ __forceinline__ uint4 pack8(const float4& a, const float4& b)
{
    __half2 h0 = __floats2half2_rn(a.x, a.y);
    __half2 h1 = __floats2half2_rn(a.z, a.w);
    __half2 h2 = __floats2half2_rn(b.x, b.y);
    __half2 h3 = __floats2half2_rn(b.z, b.w);
    uint4 o;
    o.x = *(const unsigned*)&h0;
    o.y = *(const unsigned*)&h1;
    o.z = *(const unsigned*)&h2;
    o.w = *(const unsigned*)&h3;
    return o;
}

// ---------------- merged weight conversion / padding ----------------
constexpr size_t V_IN  = HSZ_IN  / 8;
constexpr size_t V_OUT = HSZ_OUT / 8;
constexpr size_t V_XW  = (size_t)NLs * 128 * (DIm / 8);
constexpr size_t V_DW  = (size_t)NLs * DIm * (64 / 8);
constexpr size_t V_TOTAL = V_IN + V_OUT + V_XW + V_DW;

__global__ void convert_weights_kernel(const float* __restrict__ in_w,
                                       const float* __restrict__ out_w,
                                       const float* __restrict__ xw,
                                       const float* __restrict__ dw,
                                       uint4* __restrict__ wh)
{
    size_t v = (size_t)blockIdx.x * blockDim.x + threadIdx.x;
    if (v >= V_TOTAL) return;
    if (v < V_IN) {
        const float4* s = (const float4*)in_w + 2 * v;
        wh[HOFF_IN / 8 + v] = pack8(s[0], s[1]);
    } else if (v < V_IN + V_OUT) {
        size_t u = v - V_IN;
        const float4* s = (const float4*)out_w + 2 * u;
        wh[HOFF_OUT / 8 + u] = pack8(s[0], s[1]);
    } else if (v < V_IN + V_OUT + V_XW) {
        size_t u = v - V_IN - V_OUT;
        constexpr int KV = DIm / 8;
        int l = (int)(u / (128 * KV));
        int rem = (int)(u - (size_t)l * (128 * KV));
        int r = rem / KV;
        int kv = rem - r * KV;
        if (r < 80) {
            const float4* s = (const float4*)(xw + ((size_t)l * 80 + r) * DIm) + 2 * kv;
            wh[HOFF_XW / 8 + u] = pack8(s[0], s[1]);
        } else {
            wh[HOFF_XW / 8 + u] = make_uint4(0, 0, 0, 0);
        }
    } else {
        size_t u = v - V_IN - V_OUT - V_XW;
        int ld = (int)(u >> 3);       // l*DIm + d
        int cv = (int)(u & 7);
        if (cv < 6) {
            const float4* s = (const float4*)(dw + (size_t)ld * 48) + 2 * cv;
            wh[HOFF_DW / 8 + u] = pack8(s[0], s[1]);
        } else {
            wh[HOFF_DW / 8 + u] = make_uint4(0, 0, 0, 0);
        }
    }
}

// ---------------- fp32 -> fp16 plain convert (dbl16) ----------------
__global__ void f2h8_kernel(const float4* __restrict__ src, uint4* __restrict__ dst, int n8)
{
    int i = blockIdx.x * blockDim.x + threadIdx.x;
    if (i >= n8) return;
    dst[i] = pack8(src[2 * i], src[2 * i + 1]);
}

// ---------------- embedding gather ----------------
__global__ void embed_kernel(const int* __restrict__ ids,
                             const float* __restrict__ emb,
                             float* __restrict__ res)
{
    int idx = blockIdx.x * blockDim.x + threadIdx.x;
    if (idx >= Mrows * Dm) return;
    int row = idx / Dm;
    int c   = idx - row * Dm;
    res[idx] = emb[(size_t)ids[row] * Dm + c];
}

// ---------------- residual add + RMSNorm (fp16 and/or fp32 out) ----------------
__global__ void rms_resid_kernel(float* __restrict__ res,
                                 const float* __restrict__ xadd,
                                 const float* __restrict__ w,
                                 float* __restrict__ out32,
                                 __half* __restrict__ out16,
                                 int addx)
{
    const int row = blockIdx.x;
    const int tid = threadIdx.x;
    float v[3];
    float local = 0.f;
#pragma unroll
    for (int j = 0; j < 3; j++) {
        int c = tid + j * 256;
        float t = res[(size_t)row * Dm + c];
        if (addx) {
            t += xadd[(size_t)row * Dm + c];
            res[(size_t)row * Dm + c] = t;
        }
        v[j] = t;
        local += t * t;
    }
#pragma unroll
    for (int o = 16; o > 0; o >>= 1) local += __shfl_xor_sync(0xffffffffu, local, o);
    __shared__ float warpsum[8];
    __shared__ float sscale;
    if ((tid & 31) == 0) warpsum[tid >> 5] = local;
    __syncthreads();
    if (tid == 0) {
        float t = 0.f;
#pragma unroll
        for (int j = 0; j < 8; j++) t += warpsum[j];
        sscale = rsqrtf(t / (float)Dm + EPSf);
    }
    __syncthreads();
    float sc = sscale;
#pragma unroll
    for (int j = 0; j < 3; j++) {
        int c = tid + j * 256;
        float o = v[j] * sc * w[c];
        if (out32) out32[(size_t)row * Dm + c] = o;
        if (out16) out16[(size_t)row * Dm + c] = __float2half_rn(o);
    }
}

// ============================================================================
// Pure-FP16 tensor-core GEMM, fp32 accumulate, both operands via cp.async.
// C[M,N] = A[M,K](fp16, lda) @ W[N,K]^T(fp16, row stride K).
// BM=128, BN in {128,64}, BK=32.  256 threads = 8 warps (2m x 4n).
// Requires: M%128==0, N%BN==0, K%32==0, rows 16B-aligned.
// ============================================================================
template <int BN>
__global__ __launch_bounds__(256)
void hgemm16_tn(const __half* __restrict__ A, int lda,
                const __half* __restrict__ W,
                float* __restrict__ C, int ldc, int K)
{
    constexpr int BM = 128;
    constexpr int BK = 32;
    constexpr int LD = BK + 8;       // 40 halves = 80B rows
    constexpr int WM = 64;
    constexpr int WN = BN / 4;
    constexpr int AF = WM / 16;      // 4
    constexpr int BF = WN / 16;      // 2 or 1

    __shared__ __half As[2][BM][LD];
    __shared__ __half Ws[2][BN][LD];

    const int t    = threadIdx.x;
    const int warp = t >> 5;
    const int wm   = (warp & 1) * WM;
    const int wn   = (warp >> 1) * WN;
    const int bm   = blockIdx.y * BM;
    const int bn   = blockIdx.x * BN;

    // A tile: 128 rows x 32 halves = 512 vec8 units -> 2 per thread
    const int ar0 = t >> 2;              // rows t>>2 and (t>>2)+64
    const int ac  = (t & 3) * 8;
    const __half* Ap = A + (size_t)(bm + ar0) * lda + ac;
    const __half* Ap2 = Ap + (size_t)64 * lda;

    // W tile
    int wr0, wc;
    if (BN == 128) { wr0 = t >> 2; wc = (t & 3) * 8; }    // 2 units/thread
    else           { wr0 = t >> 2; wc = (t & 3) * 8; }    // 1 unit/thread
    const __half* Wp  = W + (size_t)(bn + wr0) * K + wc;
    const __half* Wp2 = (BN == 128) ? Wp + (size_t)64 * K : nullptr;

    auto issue = [&](int stage, int k0) {
        cp16(&As[stage][ar0][ac],      Ap  + k0);
        cp16(&As[stage][ar0 + 64][ac], Ap2 + k0);
        cp16(&Ws[stage][wr0][ac],      Wp  + k0);
        if (BN == 128)
            cp16(&Ws[stage][wr0 + 64][ac], Wp2 + k0);
        cp_commit();
    };

    wmma::fragment<wmma::accumulator, 16, 16, 16, float> acc[AF][BF];
#pragma unroll
    for (int i = 0; i < AF; i++)
#pragma unroll
        for (int j = 0; j < BF; j++)
            wmma::fill_fragment(acc[i][j], 0.f);

    const int nt = K / BK;

    issue(0, 0);
    cp_wait<0>();
    __syncthreads();

    for (int tt = 0; tt < nt; ++tt) {
        const int buf = tt & 1;
        const bool more = (tt + 1 < nt);
        if (more) issue(buf ^ 1, (tt + 1) * BK);

#pragma unroll
        for (int kk = 0; kk < BK; kk += 16) {
            wmma::fragment<wmma::matrix_a, 16, 16, 16, __half, wmma::row_major> af[AF];
            wmma::fragment<wmma::matrix_b, 16, 16, 16, __half, wmma::col_major> bf[BF];
#pragma unroll
            for (int i = 0; i < AF; i++)
                wmma::load_matrix_sync(af[i], &As[buf][wm + i * 16][kk], LD);
#pragma unroll
            for (int j = 0; j < BF; j++)
                wmma::load_matrix_sync(bf[j], &Ws[buf][wn + j * 16][kk], LD);
#pragma unroll
            for (int i = 0; i < AF; i++)
#pragma unroll
                for (int j = 0; j < BF; j++)
                    wmma::mma_sync(acc[i][j], af[i], bf[j], acc[i][j]);
        }

        if (more) cp_wait<0>();
        __syncthreads();
    }

#pragma unroll
    for (int i = 0; i < AF; i++)
#pragma unroll
        for (int j = 0; j < BF; j++)
            wmma::store_matrix_sync(&C[(size_t)(bm + wm + i * 16) * ldc + bn + wn + j * 16],
                                    acc[i][j], ldc, wmma::mem_row_major);
}

// ---------------- depthwise causal conv (K=4) + SiLU, fp32+fp16 out ----------------
__global__ void conv_silu_kernel(const float* __restrict__ xz,
                                 const float* __restrict__ w,
                                 const float* __restrict__ bias,
                                 float* __restrict__ xc,
                                 __half* __restrict__ xc16)
{
    int idx = blockIdx.x * blockDim.x + threadIdx.x;
    if (idx >= Mrows * DIm) return;
    int row = idx / DIm;
    int c   = idx - row * DIm;
    int l   = row & (Ll - 1);
    float s = bias[c];
#pragma unroll
    for (int k = 0; k < 4; k++) {
        int ll = l - 3 + k;
        if (ll >= 0) s += w[c * 4 + k] * xz[(size_t)(row - 3 + k) * (2 * DIm) + c];
    }
    float o = s / (1.f + expf(-s));
    xc[idx] = o;
    xc16[idx] = __float2half_rn(o);
}

// ============================================================================
// Chunked selective scan (3 phases), 4 lanes per channel, CH chunks of CL.
// ============================================================================
__device__ __forceinline__ float softplus_f(float x)
{
    return (x > 20.f) ? x : log1pf(__expf(x));
}

__global__ void scan_pass1(const float* __restrict__ xc,
                           const float* __restrict__ dtl,
                           const float* __restrict__ dbl,
                           const float* __restrict__ A_log,
                           const float* __restrict__ dtb_bias,
                           float* __restrict__ chk_end,
                           float* __restrict__ aprod)
{
    int gt = blockIdx.x * blockDim.x + threadIdx.x;
    int d = gt >> 2;
    int q = gt & 3;
    int c = blockIdx.y;
    int b = blockIdx.z;
    if (d >= DIm) return;

    float Ac[4], st[4] = {0.f, 0.f, 0.f, 0.f}, ap[4] = {1.f, 1.f, 1.f, 1.f};
#pragma unroll
    for (int n = 0; n < 4; n++)
        Ac[n] = -expf(A_log[(size_t)d * 16 + q * 4 + n]);
    const float db = dtb_bias[d];

    const int l0 = c * CL;
    const float* xcb = xc  + ((size_t)b * Ll + l0) * DIm + d;
    const float* dtb = dtl + ((size_t)b * Ll + l0) * DIm + d;
    const float* blb = dbl + ((size_t)b * Ll + l0) * DBL_LD + 48 + q * 4;

    for (int l = 0; l < CL; l++) {
        float u   = xcb[(size_t)l * DIm];
        float dtt = softplus_f(dtb[(size_t)l * DIm] + db);
        float du  = dtt * u;
        const float* bl = blb + (size_t)l * DBL_LD;
#pragma unroll
        for (int n = 0; n < 4; n++) {
            float e = __expf(dtt * Ac[n]);
            st[n] = fmaf(e, st[n], du * bl[n]);
            ap[n] *= e;
        }
    }
    size_t base = (((size_t)b * CH + c) * DIm + d) * 16 + q * 4;
#pragma unroll
    for (int n = 0; n < 4; n++) {
        chk_end[base + n] = st[n];
        aprod[base + n]   = ap[n];
    }
}

__global__ void scan_pass2(const float* __restrict__ chk_end,
                           const float* __restrict__ aprod,
                           float* __restrict__ chk_pref)
{
    int idx = blockIdx.x * blockDim.x + threadIdx.x;
    if (idx >= Bb * DIm * Nst) return;
    int b = idx / (DIm * Nst);
    int r = idx - b * (DIm * Nst);
    float hv = 0.f;
#pragma unroll
    for (int c = 0; c < CH; c++) {
        size_t o = ((size_t)b * CH + c) * DIm * Nst + r;
        chk_pref[o] = hv;
        hv = fmaf(aprod[o], hv, chk_end[o]);
    }
}

__global__ void scan_pass3(const float* __restrict__ xc,
                           const float* __restrict__ dtl,
                           const float* __restrict__ dbl,
                           const float* __restrict__ A_log,
                           const float* __restrict__ dtb_bias,
                           const float* __restrict__ Dp,
                           const float* __restrict__ xz,
                           const float* __restrict__ chk_pref,
                           __half* __restrict__ y16)
{
    int gt = blockIdx.x * blockDim.x + threadIdx.x;
    int d = gt >> 2;
    int q = gt & 3;
    int c = blockIdx.y;
    int b = blockIdx.z;
    if (d >= DIm) return;

    float Ac[4], st[4];
#pragma unroll
    for (int n = 0; n < 4; n++)
        Ac[n] = -expf(A_log[(size_t)d * 16 + q * 4 + n]);
    {
        size_t base = (((size_t)b * CH + c) * DIm + d) * 16 + q * 4;
#pragma unroll
        for (int n = 0; n < 4; n++) st[n] = chk_pref[base + n];
    }
    const float db = dtb_bias[d];
    float dp = Dp[d];

    const int l0 = c * CL;
    const float* xcb = xc  + ((size_t)b * Ll + l0) * DIm + d;
    const float* dtb = dtl + ((size_t)b * Ll + l0) * DIm + d;
    const float* zb  = xz  + ((size_t)b * Ll + l0) * (2 * DIm) + DIm + d;
    const float* blb = dbl + ((size_t)b * Ll + l0) * DBL_LD + 48 + q * 4;
    __half*      yb  = y16 + ((size_t)b * Ll + l0) * DIm + d;

    for (int l = 0; l < CL; l++) {
        float u   = xcb[(size_t)l * DIm];
        float dtt = softplus_f(dtb[(size_t)l * DIm] + db);
        float du  = dtt * u;
        const float* bl = blb + (size_t)l * DBL_LD;
        float yv = 0.f;
#pragma unroll
        for (int n = 0; n < 4; n++) {
            float e = __expf(dtt * Ac[n]);
            st[n] = fmaf(e, st[n], du * bl[n]);
            yv = fmaf(st[n], bl[16 + n], yv);
        }
        yv += __shfl_xor_sync(0xffffffffu, yv, 1);
        yv += __shfl_xor_sync(0xffffffffu, yv, 2);
        if (q == 0) {
            float z = zb[(size_t)l * (2 * DIm)];
            yv = fmaf(u, dp, yv);
            yb[(size_t)l * DIm] = __float2half_rn(yv * (z / (1.f + __expf(-z))));
        }
    }
}

// ---------------- host launcher ----------------
extern "C" void kernel_launch(void* const* d_in, const int* in_sizes, int n_in,
                              void* d_out, int out_size)
{
    const int*   ids       = (const int*)  d_in[0];
    const float* emb       = (const float*)d_in[1];
    const float* in_proj_w = (const float*)d_in[2];   // [NL, 2*DI, D]
    const float* conv_w    = (const float*)d_in[3];   // [NL, DI, 4]
    const float* conv_b    = (const float*)d_in[4];   // [NL, DI]
    const float* x_proj_w  = (const float*)d_in[5];   // [NL, 80, DI]
    const float* dt_proj_w = (const float*)d_in[6];   // [NL, DI, 48]
    const float* dt_proj_b = (const float*)d_in[7];   // [NL, DI]
    const float* A_log     = (const float*)d_in[8];   // [NL, DI, 16]
    const float* D_param   = (const float*)d_in[9];   // [NL, DI]
    const float* out_proj_w= (const float*)d_in[10];  // [NL, D, DI]
    const float* norm_w    = (const float*)d_in[11];  // [NL, D]
    const float* norm_f_w  = (const float*)d_in[12];  // [D]
    float* out = (float*)d_out;

    float* s = nullptr;
    cudaGetSymbolAddress((void**)&s, g_scratch);
    __half* wh = nullptr;
    cudaGetSymbolAddress((void**)&wh, g_wh);
    __half* ah = nullptr;
    cudaGetSymbolAddress((void**)&ah, g_act);

    float* res = s + OFF_RES;
    float* x   = s + OFF_X;
    float* xz  = s + OFF_XZ;
    float* xc  = s + OFF_XC;
    float* dtl = s + OFF_DT;
    float* dbl = s + OFF_DBL;
    float* che = s + OFF_CHE;
    float* apr = s + OFF_APR;
    float* pre = s + OFF_PRE;

    __half* w_in   = wh + HOFF_IN;
    __half* w_out  = wh + HOFF_OUT;
    __half* w_xw   = wh + HOFF_XW;
    __half* w_dw   = wh + HOFF_DW;
    __half* h16    = ah + AOFF_H16;
    __half* xc16   = ah + AOFF_XC16;
    __half* dbl16  = ah + AOFF_DBL16;
    __half* y16    = ah + AOFF_Y16;

    // 1) merged weight conversion / padding
    {
        int blocks = (int)((V_TOTAL + 255) / 256);
        convert_weights_kernel<<<blocks, 256>>>(in_proj_w, out_proj_w, x_proj_w,
                                                dt_proj_w, (uint4*)wh);
    }

    // 2) embedding
    embed_kernel<<<(Mrows * Dm + 255) / 256, 256>>>(ids, emb, res);

    for (int i = 0; i < NLs; i++) {
        // 3) h16 = fp16(rms(res += x))
        rms_resid_kernel<<<Mrows, 256>>>(res, x, norm_w + (size_t)i * Dm,
                                         nullptr, h16, i > 0);

        // 4) xz = h16 @ in_proj^T   [2048, 3072], K=768   <- profiled launch
        {
            dim3 g(2 * DIm / 128, Mrows / 128);
            hgemm16_tn<128><<<g, 256>>>(h16, Dm, w_in + (size_t)i * 2 * DIm * Dm,
                                        xz, 2 * DIm, Dm);
        }

        // xc/xc16 = silu(causal depthwise conv(xi) + b)
        conv_silu_kernel<<<(Mrows * DIm + 255) / 256, 256>>>(
            xz, conv_w + (size_t)i * DIm * 4, conv_b + (size_t)i * DIm, xc, xc16);

        // dbl = xc16 @ xw_pad^T   [2048, 128], K=1536
        {
            dim3 g(128 / 64, Mrows / 128);
            hgemm16_tn<64><<<g, 256>>>(xc16, DIm, w_xw + (size_t)i * 128 * DIm,
                                       dbl, DBL_LD, DIm);
        }

        // dbl16 = fp16(dbl)
        f2h8_kernel<<<(Mrows * DBL_LD / 8 + 255) / 256, 256>>>(
            (const float4*)dbl, (uint4*)dbl16, Mrows * DBL_LD / 8);

        // dt_lin = dbl16[:, :64] @ dw_pad^T   [2048, 1536], K=64
        {
            dim3 g(DIm / 128, Mrows / 128);
            hgemm16_tn<128><<<g, 256>>>(dbl16, DBL_LD, w_dw + (size_t)i * DIm * 64,
                                        dtl, DIm, 64);
        }

        // chunked selective scan (y emitted as fp16)
        {
            dim3 g1(DIm * 4 / 128, CH, Bb);
            scan_pass1<<<g1, 128>>>(xc, dtl, dbl, A_log + (size_t)i * DIm * Nst,
                                    dt_proj_b + (size_t)i * DIm, che, apr);
            scan_pass2<<<(Bb * DIm * Nst + 255) / 256, 256>>>(che, apr, pre);
            scan_pass3<<<g1, 128>>>(xc, dtl, dbl, A_log + (size_t)i * DIm * Nst,
                                    dt_proj_b + (size_t)i * DIm,
                                    D_param + (size_t)i * DIm, xz, pre, y16);
        }

        // x = y16 @ out_proj^T   [2048, 768], K=1536
        {
            dim3 g(Dm / 64, Mrows / 128);
            hgemm16_tn<64><<<g, 256>>>(y16, DIm, w_out + (size_t)i * Dm * DIm,
                                       x, Dm, DIm);
        }
    }

    // final: out = rms(res + x) * norm_f_w   (fp32)
    rms_resid_kernel<<<Mrows, 256>>>(res, x, norm_f_w, out, nullptr, 1);
}